// round 12
// baseline (speedup 1.0000x reference)
#include <cuda_runtime.h>
#include <cuda_fp16.h>
#include <cstdint>
#include <math.h>

// Problem constants
#define B     16
#define CIN   256
#define COUT  256
#define NE    3
#define RC    16
#define H     64
#define W     64

// ---------------------------------------------------------------------------
// Device scratch
// ---------------------------------------------------------------------------
__device__ float g_pooled[B * CIN * 16];
__device__ float g_route[B * NE * CIN];

// combined weights fp16: [b][half][pos9][chunk4][o128][c64]
#define NWH (16*2*9*4*128*64)
__device__ __align__(16) __half g_wh[NWH];

// padded transposed x, fp16: [b][yy66][xx66][c256]
#define NXT (16*66*66*256)
__device__ __align__(16) __half g_xt_h[NXT];

// ---------------------------------------------------------------------------
__device__ __forceinline__ uint32_t smem_u32(const void* p) {
    uint32_t a;
    asm("{ .reg .u64 t; cvta.to.shared.u64 t, %1; cvt.u32.u64 %0, t; }" : "=r"(a) : "l"(p));
    return a;
}
__device__ __forceinline__ void cp_async16(uint32_t dst, const void* src) {
    asm volatile("cp.async.cg.shared.global [%0], [%1], 16;" :: "r"(dst), "l"(src));
}
__device__ __forceinline__ void cp_commit() { asm volatile("cp.async.commit_group;"); }
__device__ __forceinline__ void cp_wait0() { asm volatile("cp.async.wait_group 0;"); }
__device__ __forceinline__ void cp_wait1() { asm volatile("cp.async.wait_group 1;"); }

__device__ __forceinline__ void ldsm_x4(uint32_t& r0, uint32_t& r1, uint32_t& r2, uint32_t& r3,
                                        uint32_t addr) {
    asm volatile("ldmatrix.sync.aligned.m8n8.x4.shared.b16 {%0,%1,%2,%3}, [%4];"
                 : "=r"(r0), "=r"(r1), "=r"(r2), "=r"(r3) : "r"(addr));
}
__device__ __forceinline__ void mma16816(float& c0, float& c1, float& c2, float& c3,
                                         uint32_t a0, uint32_t a1, uint32_t a2, uint32_t a3,
                                         uint32_t b0, uint32_t b1) {
    asm volatile("mma.sync.aligned.m16n8k16.row.col.f32.f16.f16.f32 "
                 "{%0,%1,%2,%3}, {%4,%5,%6,%7}, {%8,%9}, {%0,%1,%2,%3};"
                 : "+f"(c0), "+f"(c1), "+f"(c2), "+f"(c3)
                 : "r"(a0), "r"(a1), "r"(a2), "r"(a3), "r"(b0), "r"(b1));
}

// swizzled byte offset within a tile of 64-half (128B) K-rows
__device__ __forceinline__ uint32_t sw_off(int row, int seg8) {
    return (uint32_t)row * 128u + (uint32_t)((seg8 ^ (row & 7)) * 16);
}

// ---------------------------------------------------------------------------
// Kernel A: adaptive avg pool to 4x4
// ---------------------------------------------------------------------------
__global__ void pool_kernel(const float* __restrict__ x) {
    __shared__ float seg[256];
    int bc = blockIdx.x, t = threadIdx.x;
    int row = t >> 2, q = t & 3;
    const float4* b4 = reinterpret_cast<const float4*>(x + ((size_t)bc * H + row) * W + q * 16);
    float s = 0.f;
#pragma unroll
    for (int i = 0; i < 4; i++) { float4 v = b4[i]; s += v.x + v.y + v.z + v.w; }
    seg[t] = s;
    __syncthreads();
    if (t < 16) {
        int pr = t >> 2, pc = t & 3;
        float acc = 0.f;
#pragma unroll
        for (int r = 0; r < 16; r++) acc += seg[(pr * 16 + r) * 4 + pc];
        g_pooled[bc * 16 + t] = acc * (1.0f / 256.0f);
    }
}

// ---------------------------------------------------------------------------
// Kernel Z: zero padded borders of g_xt_h
// ---------------------------------------------------------------------------
#define BORDER_ELEMS (16 * 4 * 66 * 32)  // 135168
__global__ void border_kernel() {
    int i = blockIdx.x * 256 + threadIdx.x;
    if (i >= BORDER_ELEMS) return;
    int seg = i & 31;
    int idx = (i >> 5) % 66;
    int side = (i >> 5) / 66 % 4;
    int b = i / (4 * 66 * 32);
    int yy, xx;
    if (side == 0)      { yy = 0;   xx = idx; }
    else if (side == 1) { yy = 65;  xx = idx; }
    else if (side == 2) { yy = idx; xx = 0;  }
    else                { yy = idx; xx = 65; }
    size_t off = (((size_t)b * 66 + yy) * 66 + xx) * 256 + seg * 8;
    reinterpret_cast<uint4*>(&g_xt_h[off])[0] = make_uint4(0, 0, 0, 0);
}

// ---------------------------------------------------------------------------
// Kernel B: routing MLP
// ---------------------------------------------------------------------------
__global__ void route_kernel(const float* __restrict__ rconv_w,
                             const float* __restrict__ rconv_b,
                             const float* __restrict__ fc_w,
                             const float* __restrict__ fc_b) {
    __shared__ float sp[CIN * 16];
    __shared__ float sy1[RC * 16];
    int b = blockIdx.x, t = threadIdx.x;
#pragma unroll
    for (int i = 0; i < 16; i++)
        sp[t + i * 256] = g_pooled[b * CIN * 16 + t + i * 256];
    __syncthreads();
    {
        int r = t >> 4, p = t & 15;
        float s = rconv_b[r];
        const float* wrow = rconv_w + r * CIN;
#pragma unroll 8
        for (int c = 0; c < CIN; c++) s = fmaf(sp[c * 16 + p], wrow[c], s);
        sy1[r * 16 + p] = fmaxf(s, 0.f);
    }
    __syncthreads();
#pragma unroll
    for (int kk = 0; kk < NE; kk++) {
        int e = kk * 256 + t;
        float s = fc_b[e];
        const float* wrow = fc_w + (size_t)e * 256;
#pragma unroll 8
        for (int m = 0; m < 256; m++) s = fmaf(sy1[m], wrow[m], s);
        s = fmaxf(s, 0.f);
        g_route[b * (NE * CIN) + e] = 1.0f / (1.0f + expf(-s));
    }
}

// ---------------------------------------------------------------------------
// Kernel C: combine expert weights -> fp16 in A layout (single ew read)
// ---------------------------------------------------------------------------
__global__ void wsplit_kernel(const float* __restrict__ ew) {
    int idx = blockIdx.x * blockDim.x + threadIdx.x;   // 0..65535
    int o = idx >> 8, c = idx & 255;
    float w0[3][9];
#pragma unroll
    for (int k = 0; k < 3; k++)
#pragma unroll
        for (int t = 0; t < 9; t++)
            w0[k][t] = ew[(((size_t)k * COUT + o) * CIN + c) * 9 + t];
    int half = o >> 7, m = o & 127, q = c >> 6, cc = c & 63;
    for (int b = 0; b < B; b++) {
        float r0 = g_route[b * 768 + 0 * 256 + c];
        float r1 = g_route[b * 768 + 1 * 256 + c];
        float r2 = g_route[b * 768 + 2 * 256 + c];
#pragma unroll
        for (int t = 0; t < 9; t++) {
            float w = fmaf(r2, w0[2][t], fmaf(r1, w0[1][t], r0 * w0[0][t]));
            size_t off = ((((size_t)(b * 2 + half) * 9 + t) * 4 + q) * 128 + m) * 64 + cc;
            g_wh[off] = __float2half(w);
        }
    }
}

// ---------------------------------------------------------------------------
// Kernel X: transpose + pad + fp16 convert of x  ->  [b][yy][xx][c]
// ---------------------------------------------------------------------------
__global__ void xprep_kernel(const float* __restrict__ x) {
    __shared__ float ti[32][65];
    int c0 = blockIdx.x * 32, y = blockIdx.y, b = blockIdx.z;
    int t = threadIdx.x;
    {
        int cc = t >> 3, xg = t & 7;
        const float4* src = reinterpret_cast<const float4*>(
            x + (((size_t)b * CIN + c0 + cc) * H + y) * W + xg * 8);
        float4 v0 = src[0], v1 = src[1];
        ti[cc][xg * 8 + 0] = v0.x; ti[cc][xg * 8 + 1] = v0.y;
        ti[cc][xg * 8 + 2] = v0.z; ti[cc][xg * 8 + 3] = v0.w;
        ti[cc][xg * 8 + 4] = v1.x; ti[cc][xg * 8 + 5] = v1.y;
        ti[cc][xg * 8 + 6] = v1.z; ti[cc][xg * 8 + 7] = v1.w;
    }
    __syncthreads();
    int xx = t >> 2, cg = t & 3;
    __half h8[8];
#pragma unroll
    for (int j = 0; j < 8; j++)
        h8[j] = __float2half(ti[cg * 8 + j][xx]);
    size_t off = (((size_t)b * 66 + (y + 1)) * 66 + (xx + 1)) * 256 + c0 + cg * 8;
    *reinterpret_cast<uint4*>(&g_xt_h[off]) = *reinterpret_cast<const uint4*>(h8);
}

// ---------------------------------------------------------------------------
// Main conv kernel: warp-MMA fp16 shift-GEMM, XOR-swizzled smem, 2 CTAs/SM.
// SPLIT-K=2: each CTA does 2 channel chunks (128 ch), results combined via
// vector atomicAdd (float2) into pre-zeroed out. grid (32 ytile, 2 half,
// 32 = b*2 + ksplit) = 2048 CTAs -> 6.92 waves instead of 3.46 (less tail).
// ---------------------------------------------------------------------------
#define SB_BYTES  (4 * 66 * 64 * 2)        // 33792
#define SA_BYTES  (128 * 64 * 2)           // 16384
#define SMEM_TOTAL (2 * SB_BYTES + 2 * SA_BYTES)   // 100352

__global__ void __launch_bounds__(256, 2)
conv_mma_kernel(float* __restrict__ out) {
    extern __shared__ __align__(128) char smem[];
    uint32_t sB = smem_u32(smem);            // two buffers of SB_BYTES
    uint32_t sA = sB + 2 * SB_BYTES;         // two buffers of SA_BYTES

    int tid = threadIdx.x;
    int wid = tid >> 5, l = tid & 31;
    int warp_m = wid >> 2;                   // 0..1
    int warp_n = wid & 3;                    // 0..3

    int ntile = blockIdx.x;                  // 0..31
    int half  = blockIdx.y;                  // 0..1
    int zidx  = blockIdx.z;                  // 0..31
    int b     = zidx >> 1;
    int ksplt = zidx & 1;                    // channel half
    int cbase = ksplt * 2;                   // chunk base (chunks of 64 ch)
    int y0    = ntile * 2;

    int aRow    = warp_m * 64 + ((l >> 3) & 1) * 8 + (l & 7);
    uint32_t aRowByte = (uint32_t)aRow * 128u;
    int aKey    = aRow & 7;
    int kbitA   = (l >> 4) & 1;

    int bTileRow[2];
    int kbitB = (l >> 3) & 1;
#pragma unroll
    for (int g = 0; g < 2; g++) {
        int pix = warp_n * 32 + g * 16 + ((l >> 4) & 1) * 8 + (l & 7);
        int rb = pix >> 6, cb = pix & 63;
        bTileRow[g] = rb * 66 + cb;
    }

    float acc[4][4][4];
#pragma unroll
    for (int i = 0; i < 4; i++)
#pragma unroll
        for (int j = 0; j < 4; j++)
#pragma unroll
            for (int k = 0; k < 4; k++) acc[i][j][k] = 0.f;

    const __half* wbase = g_wh + (size_t)(b * 2 + half) * 9 * 4 * 128 * 64;

    auto loadB = [&](int cc, int buf) {
        uint32_t dst = sB + buf * SB_BYTES;
        int c0 = cc * 64;
        for (int i = tid; i < 264 * 8; i += 256) {
            int row = i >> 3, seg = i & 7;
            int gy = y0 + (row / 66), gx = row % 66;
            size_t goff = (((size_t)b * 66 + gy) * 66 + gx) * 256 + c0 + seg * 8;
            cp_async16(dst + sw_off(row, seg), g_xt_h + goff);
        }
    };
    auto loadA = [&](int pos, int cc, int buf) {
        uint32_t dst = sA + buf * SA_BYTES;
        for (int i = tid; i < 1024; i += 256) {
            int row = i >> 3, seg = i & 7;
            const __half* src = wbase + (((size_t)(pos * 4 + cc)) * 128 + row) * 64 + seg * 8;
            cp_async16(dst + sw_off(row, seg), src);
        }
    };

    loadB(cbase, 0);
    loadA(0, cbase, 0);
    cp_commit();
    cp_wait0();
    __syncthreads();

    for (int ccl = 0; ccl < 2; ccl++) {
        int cc = cbase + ccl;
        for (int pos = 0; pos < 9; pos++) {
            int step = ccl * 9 + pos;
            uint32_t aBase = sA + (step & 1) * SA_BYTES;
            uint32_t bBase = sB + (ccl & 1) * SB_BYTES;
            bool bpend = false;

            if (pos < 8) {
                loadA(pos + 1, cc, (step + 1) & 1);
                cp_commit();
                if (pos == 7 && ccl < 1) {
                    loadB(cc + 1, (ccl + 1) & 1);
                    cp_commit();
                    bpend = true;
                }
            } else if (ccl < 1) {
                loadA(0, cc + 1, (step + 1) & 1);
                cp_commit();
            }

            int ky = pos / 3, kx = pos % 3;
            int posRow = ky * 66 + kx;

            uint32_t bRowByte[2];
            int bKey[2];
#pragma unroll
            for (int g = 0; g < 2; g++) {
                int tr = bTileRow[g] + posRow;
                bRowByte[g] = (uint32_t)tr * 128u;
                bKey[g] = tr & 7;
            }

#pragma unroll
            for (int ks = 0; ks < 4; ks++) {
                uint32_t a0[4], a1[4], a2[4], a3[4];
                uint32_t aseg = (uint32_t)(((ks * 2 + kbitA) ^ aKey) * 16);
#pragma unroll
                for (int mf = 0; mf < 4; mf++) {
                    uint32_t addr = aBase + aRowByte + (uint32_t)(mf * 16 * 128) + aseg;
                    ldsm_x4(a0[mf], a1[mf], a2[mf], a3[mf], addr);
                }
                uint32_t bh[8];
#pragma unroll
                for (int g = 0; g < 2; g++) {
                    uint32_t addr = bBase + bRowByte[g] +
                                    (uint32_t)(((ks * 2 + kbitB) ^ bKey[g]) * 16);
                    ldsm_x4(bh[g * 4 + 0], bh[g * 4 + 1], bh[g * 4 + 2], bh[g * 4 + 3], addr);
                }
#pragma unroll
                for (int mf = 0; mf < 4; mf++) {
#pragma unroll
                    for (int nf = 0; nf < 4; nf++) {
                        int g = nf >> 1, pr = (nf & 1) * 2;
                        mma16816(acc[mf][nf][0], acc[mf][nf][1], acc[mf][nf][2], acc[mf][nf][3],
                                 a0[mf], a1[mf], a2[mf], a3[mf],
                                 bh[g * 4 + pr], bh[g * 4 + pr + 1]);
                    }
                }
            }

            if (bpend) cp_wait1();
            else       cp_wait0();
            __syncthreads();
        }
    }

    // ---- epilogue: vector atomic add into pre-zeroed out (exactly 2
    // contributions per element; fp32 add is commutative -> deterministic) ----
#pragma unroll
    for (int mf = 0; mf < 4; mf++) {
        int o = half * 128 + warp_m * 64 + mf * 16 + (l >> 2);
#pragma unroll
        for (int nf = 0; nf < 4; nf++) {
            int p = warp_n * 32 + nf * 8 + (l & 3) * 2;
            int y = y0 + (p >> 6), xcol = p & 63;
            float* base0 = out + (((size_t)b * COUT + o) * H + y) * W + xcol;
            float* base1 = out + (((size_t)b * COUT + o + 8) * H + y) * W + xcol;
            atomicAdd(reinterpret_cast<float2*>(base0),
                      make_float2(acc[mf][nf][0], acc[mf][nf][1]));
            atomicAdd(reinterpret_cast<float2*>(base1),
                      make_float2(acc[mf][nf][2], acc[mf][nf][3]));
        }
    }
}

// ---------------------------------------------------------------------------
extern "C" void kernel_launch(void* const* d_in, const int* in_sizes, int n_in,
                              void* d_out, int out_size) {
    const float* x   = (const float*)d_in[0];
    const float* ew  = (const float*)d_in[1];
    const float* rcw = (const float*)d_in[2];
    const float* rcb = (const float*)d_in[3];
    const float* fcw = (const float*)d_in[4];
    const float* fcb = (const float*)d_in[5];
    float* out = (float*)d_out;

    static cudaStream_t s2 = nullptr;
    static cudaEvent_t ev_fork = nullptr, ev_join = nullptr;
    static bool init_done = false;
    if (!init_done) {
        cudaFuncSetAttribute(conv_mma_kernel, cudaFuncAttributeMaxDynamicSharedMemorySize,
                             SMEM_TOTAL);
        cudaStreamCreateWithFlags(&s2, cudaStreamNonBlocking);
        cudaEventCreateWithFlags(&ev_fork, cudaEventDisableTiming);
        cudaEventCreateWithFlags(&ev_join, cudaEventDisableTiming);
        init_done = true;
    }

    // fork: s2 zeroes out (needed for atomic epilogue), zeroes borders,
    // and runs xprep — all concurrent with main-stream pool->route->wsplit
    cudaEventRecord(ev_fork, 0);
    cudaStreamWaitEvent(s2, ev_fork, 0);
    cudaMemsetAsync(out, 0, (size_t)out_size * sizeof(float), s2);
    border_kernel<<<(BORDER_ELEMS + 255) / 256, 256, 0, s2>>>();
    {
        dim3 g(8, 64, 16);
        xprep_kernel<<<g, 256, 0, s2>>>(x);
    }
    cudaEventRecord(ev_join, s2);

    // main stream chain
    pool_kernel<<<B * CIN, 256>>>(x);
    route_kernel<<<B, 256>>>(rcw, rcb, fcw, fcb);
    wsplit_kernel<<<256, 256>>>(ew);

    // join, then conv (split-K=2)
    cudaStreamWaitEvent(0, ev_join, 0);
    {
        dim3 g(32, 2, 32);
        conv_mma_kernel<<<g, 256, SMEM_TOTAL>>>(out);
    }
}

// round 13
// speedup vs baseline: 3.1080x; 3.1080x over previous
#include <cuda_runtime.h>
#include <cuda_fp16.h>
#include <cstdint>
#include <math.h>

// Problem constants
#define B     16
#define CIN   256
#define COUT  256
#define NE    3
#define RC    16
#define H     64
#define W     64

// ---------------------------------------------------------------------------
// Device scratch
// ---------------------------------------------------------------------------
__device__ float g_pooled[B * CIN * 16];
__device__ float g_route[B * NE * CIN];

// combined weights fp16: [b][half][pos9][chunk4][o128][c64]
#define NWH (16*2*9*4*128*64)
__device__ __align__(16) __half g_wh[NWH];

// padded transposed x, fp16: [b][yy66][xx66][c256]
#define NXT (16*66*66*256)
__device__ __align__(16) __half g_xt_h[NXT];

// ---------------------------------------------------------------------------
__device__ __forceinline__ uint32_t smem_u32(const void* p) {
    uint32_t a;
    asm("{ .reg .u64 t; cvta.to.shared.u64 t, %1; cvt.u32.u64 %0, t; }" : "=r"(a) : "l"(p));
    return a;
}
__device__ __forceinline__ void cp_async16(uint32_t dst, const void* src) {
    asm volatile("cp.async.cg.shared.global [%0], [%1], 16;" :: "r"(dst), "l"(src));
}
__device__ __forceinline__ void cp_commit() { asm volatile("cp.async.commit_group;"); }
__device__ __forceinline__ void cp_wait0() { asm volatile("cp.async.wait_group 0;"); }
__device__ __forceinline__ void cp_wait1() { asm volatile("cp.async.wait_group 1;"); }

__device__ __forceinline__ void ldsm_x4(uint32_t& r0, uint32_t& r1, uint32_t& r2, uint32_t& r3,
                                        uint32_t addr) {
    asm volatile("ldmatrix.sync.aligned.m8n8.x4.shared.b16 {%0,%1,%2,%3}, [%4];"
                 : "=r"(r0), "=r"(r1), "=r"(r2), "=r"(r3) : "r"(addr));
}
__device__ __forceinline__ void mma16816(float& c0, float& c1, float& c2, float& c3,
                                         uint32_t a0, uint32_t a1, uint32_t a2, uint32_t a3,
                                         uint32_t b0, uint32_t b1) {
    asm volatile("mma.sync.aligned.m16n8k16.row.col.f32.f16.f16.f32 "
                 "{%0,%1,%2,%3}, {%4,%5,%6,%7}, {%8,%9}, {%0,%1,%2,%3};"
                 : "+f"(c0), "+f"(c1), "+f"(c2), "+f"(c3)
                 : "r"(a0), "r"(a1), "r"(a2), "r"(a3), "r"(b0), "r"(b1));
}

// swizzled byte offset within a tile of 64-half (128B) K-rows
__device__ __forceinline__ uint32_t sw_off(int row, int seg8) {
    return (uint32_t)row * 128u + (uint32_t)((seg8 ^ (row & 7)) * 16);
}

// ---------------------------------------------------------------------------
// Kernel A+Z merged: pool (blocks 0..4095) + border zeroing (blocks 4096..)
// ---------------------------------------------------------------------------
#define POOL_BLOCKS (B * CIN)            // 4096
#define BORDER_ELEMS (16 * 4 * 66 * 32)  // 135168
#define BORDER_BLOCKS ((BORDER_ELEMS + 255) / 256)   // 528

__global__ void prep0_kernel(const float* __restrict__ x) {
    if (blockIdx.x < POOL_BLOCKS) {
        __shared__ float seg[256];
        int bc = blockIdx.x, t = threadIdx.x;
        int row = t >> 2, q = t & 3;
        const float4* b4 = reinterpret_cast<const float4*>(x + ((size_t)bc * H + row) * W + q * 16);
        float s = 0.f;
#pragma unroll
        for (int i = 0; i < 4; i++) { float4 v = b4[i]; s += v.x + v.y + v.z + v.w; }
        seg[t] = s;
        __syncthreads();
        if (t < 16) {
            int pr = t >> 2, pc = t & 3;
            float acc = 0.f;
#pragma unroll
            for (int r = 0; r < 16; r++) acc += seg[(pr * 16 + r) * 4 + pc];
            g_pooled[bc * 16 + t] = acc * (1.0f / 256.0f);
        }
    } else {
        int i = (blockIdx.x - POOL_BLOCKS) * 256 + threadIdx.x;
        if (i >= BORDER_ELEMS) return;
        int seg = i & 31;
        int idx = (i >> 5) % 66;
        int side = (i >> 5) / 66 % 4;
        int b = i / (4 * 66 * 32);
        int yy, xx;
        if (side == 0)      { yy = 0;   xx = idx; }
        else if (side == 1) { yy = 65;  xx = idx; }
        else if (side == 2) { yy = idx; xx = 0;  }
        else                { yy = idx; xx = 65; }
        size_t off = (((size_t)b * 66 + yy) * 66 + xx) * 256 + seg * 8;
        reinterpret_cast<uint4*>(&g_xt_h[off])[0] = make_uint4(0, 0, 0, 0);
    }
}

// ---------------------------------------------------------------------------
// Kernel B: routing MLP
// ---------------------------------------------------------------------------
__global__ void route_kernel(const float* __restrict__ rconv_w,
                             const float* __restrict__ rconv_b,
                             const float* __restrict__ fc_w,
                             const float* __restrict__ fc_b) {
    __shared__ float sp[CIN * 16];
    __shared__ float sy1[RC * 16];
    int b = blockIdx.x, t = threadIdx.x;
#pragma unroll
    for (int i = 0; i < 16; i++)
        sp[t + i * 256] = g_pooled[b * CIN * 16 + t + i * 256];
    __syncthreads();
    {
        int r = t >> 4, p = t & 15;
        float s = rconv_b[r];
        const float* wrow = rconv_w + r * CIN;
#pragma unroll 8
        for (int c = 0; c < CIN; c++) s = fmaf(sp[c * 16 + p], wrow[c], s);
        sy1[r * 16 + p] = fmaxf(s, 0.f);
    }
    __syncthreads();
#pragma unroll
    for (int kk = 0; kk < NE; kk++) {
        int e = kk * 256 + t;
        float s = fc_b[e];
        const float* wrow = fc_w + (size_t)e * 256;
#pragma unroll 8
        for (int m = 0; m < 256; m++) s = fmaf(sy1[m], wrow[m], s);
        s = fmaxf(s, 0.f);
        g_route[b * (NE * CIN) + e] = 1.0f / (1.0f + expf(-s));
    }
}

// ---------------------------------------------------------------------------
// Kernel C: combine expert weights -> fp16 in A layout (single ew read)
// ---------------------------------------------------------------------------
__global__ void wsplit_kernel(const float* __restrict__ ew) {
    int idx = blockIdx.x * blockDim.x + threadIdx.x;   // 0..65535
    int o = idx >> 8, c = idx & 255;
    float w0[3][9];
#pragma unroll
    for (int k = 0; k < 3; k++)
#pragma unroll
        for (int t = 0; t < 9; t++)
            w0[k][t] = ew[(((size_t)k * COUT + o) * CIN + c) * 9 + t];
    int half = o >> 7, m = o & 127, q = c >> 6, cc = c & 63;
    for (int b = 0; b < B; b++) {
        float r0 = g_route[b * 768 + 0 * 256 + c];
        float r1 = g_route[b * 768 + 1 * 256 + c];
        float r2 = g_route[b * 768 + 2 * 256 + c];
#pragma unroll
        for (int t = 0; t < 9; t++) {
            float w = fmaf(r2, w0[2][t], fmaf(r1, w0[1][t], r0 * w0[0][t]));
            size_t off = ((((size_t)(b * 2 + half) * 9 + t) * 4 + q) * 128 + m) * 64 + cc;
            g_wh[off] = __float2half(w);
        }
    }
}

// ---------------------------------------------------------------------------
// Kernel X: transpose + pad + fp16 convert of x  ->  [b][yy][xx][c]
// ---------------------------------------------------------------------------
__global__ void xprep_kernel(const float* __restrict__ x) {
    __shared__ float ti[32][65];
    int c0 = blockIdx.x * 32, y = blockIdx.y, b = blockIdx.z;
    int t = threadIdx.x;
    {
        int cc = t >> 3, xg = t & 7;
        const float4* src = reinterpret_cast<const float4*>(
            x + (((size_t)b * CIN + c0 + cc) * H + y) * W + xg * 8);
        float4 v0 = src[0], v1 = src[1];
        ti[cc][xg * 8 + 0] = v0.x; ti[cc][xg * 8 + 1] = v0.y;
        ti[cc][xg * 8 + 2] = v0.z; ti[cc][xg * 8 + 3] = v0.w;
        ti[cc][xg * 8 + 4] = v1.x; ti[cc][xg * 8 + 5] = v1.y;
        ti[cc][xg * 8 + 6] = v1.z; ti[cc][xg * 8 + 7] = v1.w;
    }
    __syncthreads();
    int xx = t >> 2, cg = t & 3;
    __half h8[8];
#pragma unroll
    for (int j = 0; j < 8; j++)
        h8[j] = __float2half(ti[cg * 8 + j][xx]);
    size_t off = (((size_t)b * 66 + (y + 1)) * 66 + (xx + 1)) * 256 + c0 + cg * 8;
    *reinterpret_cast<uint4*>(&g_xt_h[off]) = *reinterpret_cast<const uint4*>(h8);
}

// ---------------------------------------------------------------------------
// Main conv kernel: warp-MMA fp16 shift-GEMM, XOR-swizzled smem, 2 CTAs/SM.
// CTA: M=128 couts x N=128 px (2 output rows). 8 warps (2x4), warp 64x32.
// ---------------------------------------------------------------------------
#define SB_BYTES  (4 * 66 * 64 * 2)        // 33792
#define SA_BYTES  (128 * 64 * 2)           // 16384
#define SMEM_TOTAL (2 * SB_BYTES + 2 * SA_BYTES)   // 100352

__global__ void __launch_bounds__(256, 2)
conv_mma_kernel(float* __restrict__ out) {
    extern __shared__ __align__(128) char smem[];
    uint32_t sB = smem_u32(smem);            // two buffers of SB_BYTES
    uint32_t sA = sB + 2 * SB_BYTES;         // two buffers of SA_BYTES

    int tid = threadIdx.x;
    int wid = tid >> 5, l = tid & 31;
    int warp_m = wid >> 2;                   // 0..1
    int warp_n = wid & 3;                    // 0..3

    int ntile = blockIdx.x;                  // 0..31
    int half  = blockIdx.y;                  // 0..1
    int b     = blockIdx.z;                  // 0..15
    int y0    = ntile * 2;

    int aRow    = warp_m * 64 + ((l >> 3) & 1) * 8 + (l & 7);
    uint32_t aRowByte = (uint32_t)aRow * 128u;
    int aKey    = aRow & 7;
    int kbitA   = (l >> 4) & 1;

    int bTileRow[2];
    int kbitB = (l >> 3) & 1;
#pragma unroll
    for (int g = 0; g < 2; g++) {
        int pix = warp_n * 32 + g * 16 + ((l >> 4) & 1) * 8 + (l & 7);
        int rb = pix >> 6, cb = pix & 63;
        bTileRow[g] = rb * 66 + cb;
    }

    float acc[4][4][4];
#pragma unroll
    for (int i = 0; i < 4; i++)
#pragma unroll
        for (int j = 0; j < 4; j++)
#pragma unroll
            for (int k = 0; k < 4; k++) acc[i][j][k] = 0.f;

    const __half* wbase = g_wh + (size_t)(b * 2 + half) * 9 * 4 * 128 * 64;

    auto loadB = [&](int cc, int buf) {
        uint32_t dst = sB + buf * SB_BYTES;
        int c0 = cc * 64;
        for (int i = tid; i < 264 * 8; i += 256) {
            int row = i >> 3, seg = i & 7;
            int gy = y0 + (row / 66), gx = row % 66;
            size_t goff = (((size_t)b * 66 + gy) * 66 + gx) * 256 + c0 + seg * 8;
            cp_async16(dst + sw_off(row, seg), g_xt_h + goff);
        }
    };
    auto loadA = [&](int pos, int cc, int buf) {
        uint32_t dst = sA + buf * SA_BYTES;
        for (int i = tid; i < 1024; i += 256) {
            int row = i >> 3, seg = i & 7;
            const __half* src = wbase + (((size_t)(pos * 4 + cc)) * 128 + row) * 64 + seg * 8;
            cp_async16(dst + sw_off(row, seg), src);
        }
    };

    loadB(0, 0);
    loadA(0, 0, 0);
    cp_commit();
    cp_wait0();
    __syncthreads();

    for (int cc = 0; cc < 4; cc++) {
        for (int pos = 0; pos < 9; pos++) {
            int step = cc * 9 + pos;
            uint32_t aBase = sA + (step & 1) * SA_BYTES;
            uint32_t bBase = sB + (cc & 1) * SB_BYTES;
            bool bpend = false;

            if (pos < 8) {
                loadA(pos + 1, cc, (step + 1) & 1);
                cp_commit();
                if (pos == 7 && cc < 3) {
                    loadB(cc + 1, (cc + 1) & 1);
                    cp_commit();
                    bpend = true;
                }
            } else if (cc < 3) {
                loadA(0, cc + 1, (step + 1) & 1);
                cp_commit();
            }

            int ky = pos / 3, kx = pos % 3;
            int posRow = ky * 66 + kx;

            uint32_t bRowByte[2];
            int bKey[2];
#pragma unroll
            for (int g = 0; g < 2; g++) {
                int tr = bTileRow[g] + posRow;
                bRowByte[g] = (uint32_t)tr * 128u;
                bKey[g] = tr & 7;
            }

#pragma unroll
            for (int ks = 0; ks < 4; ks++) {
                uint32_t a0[4], a1[4], a2[4], a3[4];
                uint32_t aseg = (uint32_t)(((ks * 2 + kbitA) ^ aKey) * 16);
#pragma unroll
                for (int mf = 0; mf < 4; mf++) {
                    uint32_t addr = aBase + aRowByte + (uint32_t)(mf * 16 * 128) + aseg;
                    ldsm_x4(a0[mf], a1[mf], a2[mf], a3[mf], addr);
                }
                uint32_t bh[8];
#pragma unroll
                for (int g = 0; g < 2; g++) {
                    uint32_t addr = bBase + bRowByte[g] +
                                    (uint32_t)(((ks * 2 + kbitB) ^ bKey[g]) * 16);
                    ldsm_x4(bh[g * 4 + 0], bh[g * 4 + 1], bh[g * 4 + 2], bh[g * 4 + 3], addr);
                }
#pragma unroll
                for (int mf = 0; mf < 4; mf++) {
#pragma unroll
                    for (int nf = 0; nf < 4; nf++) {
                        int g = nf >> 1, pr = (nf & 1) * 2;
                        mma16816(acc[mf][nf][0], acc[mf][nf][1], acc[mf][nf][2], acc[mf][nf][3],
                                 a0[mf], a1[mf], a2[mf], a3[mf],
                                 bh[g * 4 + pr], bh[g * 4 + pr + 1]);
                    }
                }
            }

            if (bpend) cp_wait1();
            else       cp_wait0();
            __syncthreads();
        }
    }

    // ---- epilogue ----
#pragma unroll
    for (int mf = 0; mf < 4; mf++) {
        int o = half * 128 + warp_m * 64 + mf * 16 + (l >> 2);
#pragma unroll
        for (int nf = 0; nf < 4; nf++) {
            int p = warp_n * 32 + nf * 8 + (l & 3) * 2;
            int y = y0 + (p >> 6), xcol = p & 63;
            float* base0 = out + (((size_t)b * COUT + o) * H + y) * W + xcol;
            float* base1 = out + (((size_t)b * COUT + o + 8) * H + y) * W + xcol;
            reinterpret_cast<float2*>(base0)[0] = make_float2(acc[mf][nf][0], acc[mf][nf][1]);
            reinterpret_cast<float2*>(base1)[0] = make_float2(acc[mf][nf][2], acc[mf][nf][3]);
        }
    }
}

// ---------------------------------------------------------------------------
extern "C" void kernel_launch(void* const* d_in, const int* in_sizes, int n_in,
                              void* d_out, int out_size) {
    const float* x   = (const float*)d_in[0];
    const float* ew  = (const float*)d_in[1];
    const float* rcw = (const float*)d_in[2];
    const float* rcb = (const float*)d_in[3];
    const float* fcw = (const float*)d_in[4];
    const float* fcb = (const float*)d_in[5];
    float* out = (float*)d_out;

    static cudaStream_t s2 = nullptr;
    static cudaEvent_t ev_fork = nullptr, ev_join = nullptr;
    static bool init_done = false;
    if (!init_done) {
        cudaFuncSetAttribute(conv_mma_kernel, cudaFuncAttributeMaxDynamicSharedMemorySize,
                             SMEM_TOTAL);
        cudaStreamCreateWithFlags(&s2, cudaStreamNonBlocking);
        cudaEventCreateWithFlags(&ev_fork, cudaEventDisableTiming);
        cudaEventCreateWithFlags(&ev_join, cudaEventDisableTiming);
        init_done = true;
    }

    // fork: xprep runs on side stream, concurrent with prep0->route->wsplit
    cudaEventRecord(ev_fork, 0);
    cudaStreamWaitEvent(s2, ev_fork, 0);
    {
        dim3 g(8, 64, 16);
        xprep_kernel<<<g, 256, 0, s2>>>(x);
    }
    cudaEventRecord(ev_join, s2);

    // main stream chain
    prep0_kernel<<<POOL_BLOCKS + BORDER_BLOCKS, 256>>>(x);
    route_kernel<<<B, 256>>>(rcw, rcb, fcw, fcb);
    wsplit_kernel<<<256, 256>>>(ew);

    // join, then conv
    cudaStreamWaitEvent(0, ev_join, 0);
    {
        dim3 g(32, 2, 16);
        conv_mma_kernel<<<g, 256, SMEM_TOTAL>>>(out);
    }
}